// round 1
// baseline (speedup 1.0000x reference)
#include <cuda_runtime.h>

// NavierStokesLossMAC: fused residual + masked MSE over interior, per batch.
// Shapes: v_old/v_new (8,2,1024,1024) f32, p_new (8,1,1024,1024) f32,
//         flow_mask_mac (8,1,1024,1024) i32. Output: (8,) f32.

static constexpr int B = 8;
static constexpr int H = 1024;
static constexpr int W = 1024;
static constexpr float MU = 0.1f;
static constexpr float INV_DT = 0.25f;   // 1/DT, DT=4

__device__ double g_accum[B];

__global__ void ns_zero_kernel() {
    if (threadIdx.x < B) g_accum[threadIdx.x] = 0.0;
}

__global__ __launch_bounds__(256) void ns_loss_kernel(
    const float* __restrict__ v_old,
    const float* __restrict__ v_new,
    const float* __restrict__ p_new,
    const int*   __restrict__ mask)
{
    const int b  = blockIdx.z;
    const int y  = blockIdx.y + 1;        // interior rows 1..H-2
    const int x0 = threadIdx.x * 4;       // quad of pixels x0..x0+3

    const size_t plane = (size_t)H * W;
    const float* uo = v_old + (size_t)b * 2 * plane;      // v_old[:,0] = u
    const float* wo = uo + plane;                          // v_old[:,1] = w
    const float* un = v_new + (size_t)b * 2 * plane;
    const float* wn = un + plane;
    const float* pp = p_new + (size_t)b * plane;
    const int*   mm = mask  + (size_t)b * plane;

    const int row = y * W;
    const int rym = row - W;
    const int ryp = row + W;

    // ---- center-row loads (need x0-1 .. x0+4) ----
    float4 uo_c = *(const float4*)(uo + row + x0);
    float4 un_c = *(const float4*)(un + row + x0);
    float4 wo_c = *(const float4*)(wo + row + x0);
    float4 wn_c = *(const float4*)(wn + row + x0);
    // boundary scalars: x0-1 and x0+4. y in [1,H-2] guarantees these indices
    // stay inside the (b,channel) plane (they may read a neighboring row's
    // edge value, which is only ever used for pixels we exclude from the sum).
    float uo_l = uo[row + x0 - 1], un_l = un[row + x0 - 1];
    float uo_r = uo[row + x0 + 4], un_r = un[row + x0 + 4];
    float wo_l = wo[row + x0 - 1], wn_l = wn[row + x0 - 1];
    float wo_r = wo[row + x0 + 4], wn_r = wn[row + x0 + 4];

    // ---- y-1 / y+1 row loads (x0 .. x0+3) ----
    float4 uo_m = *(const float4*)(uo + rym + x0);
    float4 un_m = *(const float4*)(un + rym + x0);
    float4 uo_p = *(const float4*)(uo + ryp + x0);
    float4 un_p = *(const float4*)(un + ryp + x0);
    float4 wo_m = *(const float4*)(wo + rym + x0);
    float4 wn_m = *(const float4*)(wn + rym + x0);
    float4 wo_p = *(const float4*)(wo + ryp + x0);
    float4 wn_p = *(const float4*)(wn + ryp + x0);

    // ---- pressure / mask ----
    float4 p_c4 = *(const float4*)(pp + row + x0);
    float  p_l  = pp[row + x0 - 1];
    float4 p_m4 = *(const float4*)(pp + rym + x0);
    int4   mk   = *(const int4*)(mm + row + x0);

    // time-averaged velocities v = 0.5*(v_new + v_old)
    float uc6[6], wc6[6];
    uc6[0] = 0.5f * (uo_l + un_l);
    uc6[1] = 0.5f * (uo_c.x + un_c.x);
    uc6[2] = 0.5f * (uo_c.y + un_c.y);
    uc6[3] = 0.5f * (uo_c.z + un_c.z);
    uc6[4] = 0.5f * (uo_c.w + un_c.w);
    uc6[5] = 0.5f * (uo_r + un_r);
    wc6[0] = 0.5f * (wo_l + wn_l);
    wc6[1] = 0.5f * (wo_c.x + wn_c.x);
    wc6[2] = 0.5f * (wo_c.y + wn_c.y);
    wc6[3] = 0.5f * (wo_c.z + wn_c.z);
    wc6[4] = 0.5f * (wo_c.w + wn_c.w);
    wc6[5] = 0.5f * (wo_r + wn_r);

    float uym[4] = {0.5f*(uo_m.x+un_m.x), 0.5f*(uo_m.y+un_m.y), 0.5f*(uo_m.z+un_m.z), 0.5f*(uo_m.w+un_m.w)};
    float uyp[4] = {0.5f*(uo_p.x+un_p.x), 0.5f*(uo_p.y+un_p.y), 0.5f*(uo_p.z+un_p.z), 0.5f*(uo_p.w+un_p.w)};
    float wym[4] = {0.5f*(wo_m.x+wn_m.x), 0.5f*(wo_m.y+wn_m.y), 0.5f*(wo_m.z+wn_m.z), 0.5f*(wo_m.w+wn_m.w)};
    float wyp[4] = {0.5f*(wo_p.x+wn_p.x), 0.5f*(wo_p.y+wn_p.y), 0.5f*(wo_p.z+wn_p.z), 0.5f*(wo_p.w+wn_p.w)};

    float udt[4] = {(un_c.x-uo_c.x)*INV_DT, (un_c.y-uo_c.y)*INV_DT, (un_c.z-uo_c.z)*INV_DT, (un_c.w-uo_c.w)*INV_DT};
    float wdt[4] = {(wn_c.x-wo_c.x)*INV_DT, (wn_c.y-wo_c.y)*INV_DT, (wn_c.z-wo_c.z)*INV_DT, (wn_c.w-wo_c.w)*INV_DT};

    float pc5[5] = {p_l, p_c4.x, p_c4.y, p_c4.z, p_c4.w};
    float pym[4] = {p_m4.x, p_m4.y, p_m4.z, p_m4.w};
    int   mk4[4] = {mk.x, mk.y, mk.z, mk.w};

    float local = 0.0f;
    #pragma unroll
    for (int j = 0; j < 4; ++j) {
        const float u_c  = uc6[j+1], u_xm = uc6[j], u_xp = uc6[j+2];
        const float w_c  = wc6[j+1], w_xm = wc6[j], w_xp = wc6[j+2];
        const float u_ym = uym[j],  u_yp = uyp[j];
        const float w_ym = wym[j],  w_yp = wyp[j];

        // res_x  (RHO = 1)
        float rx = wdt[j]
                 + w_c * 0.5f * (w_xp - w_xm)
                 + 0.5f * ( 0.5f*(u_c + u_xm) * (w_c - w_ym)
                          + 0.5f*(u_c + u_xp) * (w_yp - w_c) )
                 + (pc5[j+1] - pc5[j])
                 - MU * (w_xm + w_xp + w_ym + w_yp - 4.0f * w_c);

        // res_y
        float ry = udt[j]
                 + u_c * 0.5f * (u_yp - u_ym)
                 + 0.5f * ( 0.5f*(w_c + w_ym) * (u_c - u_xm)
                          + 0.5f*(w_c + w_yp) * (u_xp - u_c) )
                 + (pc5[j+1] - pym[j])
                 - MU * (u_xm + u_xp + u_ym + u_yp - 4.0f * u_c);

        const float mf = (float)mk4[j];
        rx *= mf;
        ry *= mf;

        const int x = x0 + j;
        if (x >= 1 && x <= W - 2)        // only interior contributes (also keeps
            local += rx * rx + ry * ry;  // edge garbage/NaN out of the sum)
    }

    // ---- block reduction ----
    #pragma unroll
    for (int o = 16; o > 0; o >>= 1)
        local += __shfl_xor_sync(0xffffffffu, local, o);

    __shared__ float s_part[8];
    const int lane = threadIdx.x & 31;
    const int wid  = threadIdx.x >> 5;
    if (lane == 0) s_part[wid] = local;
    __syncthreads();
    if (wid == 0) {
        float v = (lane < 8) ? s_part[lane] : 0.0f;
        #pragma unroll
        for (int o = 4; o > 0; o >>= 1)
            v += __shfl_xor_sync(0xffffffffu, v, o);
        if (lane == 0)
            atomicAdd(&g_accum[b], (double)v);
    }
}

__global__ void ns_fin_kernel(float* __restrict__ out) {
    if (threadIdx.x < B) {
        const double inv_cnt = 1.0 / ((double)(H - 2) * (double)(W - 2));
        out[threadIdx.x] = (float)(g_accum[threadIdx.x] * inv_cnt);
    }
}

extern "C" void kernel_launch(void* const* d_in, const int* in_sizes, int n_in,
                              void* d_out, int out_size) {
    const float* v_old = (const float*)d_in[0];
    const float* v_new = (const float*)d_in[1];
    const float* p_new = (const float*)d_in[2];
    const int*   mask  = (const int*)d_in[3];
    float* out = (float*)d_out;

    ns_zero_kernel<<<1, 32>>>();
    dim3 grid(1, H - 2, B);       // one block per interior row per batch
    ns_loss_kernel<<<grid, 256>>>(v_old, v_new, p_new, mask);
    ns_fin_kernel<<<1, 32>>>(out);
}